// round 11
// baseline (speedup 1.0000x reference)
#include <cuda_runtime.h>
#include <cstdint>

// Problem constants
#define Bn 64
#define Tn 512
#define Dn 1024
#define Cn 32
#define BT (Bn*Tn)          // 32768

// Scratch (small, no device allocation allowed)
__device__ float g_logZ[Bn];
__device__ float g_score[Bn];
__device__ int   g_msum[Bn];

// ---------------------------------------------------------------------------
// packed f32x2 helpers (Blackwell sm_100+)
// ---------------------------------------------------------------------------
__device__ __forceinline__ unsigned long long pack2(float lo, float hi) {
    unsigned long long r;
    asm("mov.b64 %0, {%1, %2};" : "=l"(r) : "f"(lo), "f"(hi));
    return r;
}
__device__ __forceinline__ void fma2(unsigned long long& d, unsigned long long a, unsigned long long b) {
    asm("fma.rn.f32x2 %0, %1, %2, %0;" : "+l"(d) : "l"(a), "l"(b));
}
__device__ __forceinline__ void unpack2(unsigned long long v, float& lo, float& hi) {
    asm("mov.b64 {%0, %1}, %2;" : "=f"(lo), "=f"(hi) : "l"(v));
}

// ---------------------------------------------------------------------------
// Kernel 1: logits[r][c] = sum_d V[r][d] * W[c][d] + b[c]
//   r in [0, 32768), c in [0, 32), d in [0, 1024)
//   One thread per row; W staged through smem in 4 chunks of 256 K.
// ---------------------------------------------------------------------------
__device__ __forceinline__ void do_k(float vs, const float* swk, unsigned long long* acc) {
    unsigned long long vv = pack2(vs, vs);
    const ulonglong2* sw = reinterpret_cast<const ulonglong2*>(swk);
#pragma unroll
    for (int q = 0; q < 8; q++) {
        ulonglong2 w = sw[q];
        fma2(acc[2*q],   vv, w.x);
        fma2(acc[2*q+1], vv, w.y);
    }
}

__global__ __launch_bounds__(256) void gemm_kernel(
    const float* __restrict__ V,   // [BT, D]
    const float* __restrict__ W,   // [C, D]
    const float* __restrict__ bias,// [C]
    float* __restrict__ out)       // [BT, C]  (== d_out + 1, 4B aligned only)
{
    __shared__ __align__(16) float sW[256 * 32];   // 32 KB: Wt[k_local][c]

    const int tid = threadIdx.x;
    const int row = blockIdx.x * 256 + tid;

    unsigned long long acc[16];
#pragma unroll
    for (int p = 0; p < 16; p++) acc[p] = pack2(bias[2*p], bias[2*p+1]);

    const float4* vp = reinterpret_cast<const float4*>(V + (size_t)row * Dn);

    for (int kc = 0; kc < 4; kc++) {
        __syncthreads();
        // stage Wt chunk: sW[kl*32 + c] = W[c*1024 + kc*256 + kl]
#pragma unroll 4
        for (int i = tid; i < 8192; i += 256) {
            int c  = i & 31;
            int kl = i >> 5;
            sW[i] = W[c * Dn + kc * 256 + kl];
        }
        __syncthreads();

        float4 v = vp[kc * 64];
#pragma unroll 2
        for (int k4 = 0; k4 < 64; k4++) {
            float4 vn = v;
            if (k4 < 63) vn = vp[kc * 64 + k4 + 1];
            const float* swb = sW + (k4 * 4) * 32;
            do_k(v.x, swb,      acc);
            do_k(v.y, swb + 32, acc);
            do_k(v.z, swb + 64, acc);
            do_k(v.w, swb + 96, acc);
            v = vn;
        }
    }

    // Scalar stores (out base is only 4B-aligned).
    float* orow = out + (size_t)row * Cn;
#pragma unroll
    for (int p = 0; p < 16; p++) {
        float f0, f1;
        unpack2(acc[p], f0, f1);
        orow[2*p]     = f0;
        orow[2*p + 1] = f1;
    }
}

// ---------------------------------------------------------------------------
// Kernel 2: 192 one-warp blocks.
//   blocks [0,64):    forward log-sum-exp recursion -> g_logZ[b]
//   blocks [64,128):  Viterbi recursion + backtrace -> tags, path_scores
//   blocks [128,192): gold score -> g_score[b], g_msum[b]
// ---------------------------------------------------------------------------
__global__ __launch_bounds__(32) void crf_kernel(
    const float* __restrict__ logits,  // [B, T, C]
    const int*   __restrict__ mask,    // [B, T]
    const int*   __restrict__ targets, // [B, T]
    const float* __restrict__ trans,   // [C, C]
    const float* __restrict__ startt,  // [C]
    const float* __restrict__ endt,    // [C]
    float* __restrict__ tags_out,      // [B, T] as float
    float* __restrict__ path_out)      // [B]
{
    __shared__ unsigned char bp[(Tn - 1) * Cn];  // 16352 B backpointers
    __shared__ unsigned char tg[Tn];

    const unsigned FULL = 0xffffffffu;
    const int j = threadIdx.x;
    const int bid = blockIdx.x;

    if (bid < 64) {
        // ---------------- forward (log-sum-exp) ----------------
        const int b = bid;
        float E[32];
#pragma unroll
        for (int i = 0; i < 32; i++) E[i] = __expf(trans[i * Cn + j]);

        const float* lg = logits + (size_t)b * Tn * Cn + j;
        const int*   mk = mask + b * Tn;

        float alpha = startt[j] + lg[0];
        float lt1 = lg[1 * Cn];  int m1 = mk[1];
        float lt2 = lg[2 * Cn];  int m2 = mk[2];

        for (int t = 1; t < Tn; t++) {
            float lt = lt1; int mt = m1;
            lt1 = lt2; m1 = m2;
            if (t + 2 < Tn) { lt2 = lg[(t + 2) * Cn]; m2 = mk[t + 2]; }

            float a0 = __shfl_sync(FULL, alpha, 0);
            float p  = __expf(alpha - a0);
            float s0 = 0.f, s1 = 0.f, s2 = 0.f, s3 = 0.f;
#pragma unroll
            for (int i = 0; i < 32; i += 4) {
                s0 = fmaf(__shfl_sync(FULL, p, i),     E[i],     s0);
                s1 = fmaf(__shfl_sync(FULL, p, i + 1), E[i + 1], s1);
                s2 = fmaf(__shfl_sync(FULL, p, i + 2), E[i + 2], s2);
                s3 = fmaf(__shfl_sync(FULL, p, i + 3), E[i + 3], s3);
            }
            float s = (s0 + s1) + (s2 + s3);
            float anew = a0 + __logf(s) + lt;
            alpha = (mt > 0) ? anew : alpha;
        }

        // logZ = LSE(alpha + end)
        float v = alpha + endt[j];
        float m = v;
#pragma unroll
        for (int o = 16; o; o >>= 1) m = fmaxf(m, __shfl_xor_sync(FULL, m, o));
        float e = __expf(v - m);
#pragma unroll
        for (int o = 16; o; o >>= 1) e += __shfl_xor_sync(FULL, e, o);
        if (j == 0) g_logZ[b] = m + __logf(e);

    } else if (bid < 128) {
        // ---------------- Viterbi ----------------
        const int b = bid - 64;
        float Tr[32];
#pragma unroll
        for (int i = 0; i < 32; i++) Tr[i] = trans[i * Cn + j];

        const float* lg = logits + (size_t)b * Tn * Cn + j;
        const int*   mk = mask + b * Tn;

        float delta = startt[j] + lg[0];
        float lt1 = lg[1 * Cn];  int m1 = mk[1];
        float lt2 = lg[2 * Cn];  int m2 = mk[2];

        for (int t = 1; t < Tn; t++) {
            float lt = lt1; int mt = m1;
            lt1 = lt2; m1 = m2;
            if (t + 2 < Tn) { lt2 = lg[(t + 2) * Cn]; m2 = mk[t + 2]; }

            float cand[32];
#pragma unroll
            for (int i = 0; i < 32; i++)
                cand[i] = __shfl_sync(FULL, delta, i) + Tr[i];

            // exact max tree (FMNMX is exact; order irrelevant for max)
            float tr0[16];
#pragma unroll
            for (int i = 0; i < 16; i++) tr0[i] = fmaxf(cand[2*i], cand[2*i+1]);
#pragma unroll
            for (int i = 0; i < 8; i++)  tr0[i] = fmaxf(tr0[2*i], tr0[2*i+1]);
#pragma unroll
            for (int i = 0; i < 4; i++)  tr0[i] = fmaxf(tr0[2*i], tr0[2*i+1]);
            tr0[0] = fmaxf(tr0[0], tr0[1]);
            tr0[1] = fmaxf(tr0[2], tr0[3]);
            float mval = fmaxf(tr0[0], tr0[1]);

            // first-argmax: lowest i with cand[i] == max
            unsigned e0 = 0, e1 = 0, e2 = 0, e3 = 0;
#pragma unroll
            for (int i = 0; i < 32; i += 4) {
                e0 |= (cand[i]     == mval) ? (1u << i)       : 0u;
                e1 |= (cand[i + 1] == mval) ? (1u << (i + 1)) : 0u;
                e2 |= (cand[i + 2] == mval) ? (1u << (i + 2)) : 0u;
                e3 |= (cand[i + 3] == mval) ? (1u << (i + 3)) : 0u;
            }
            int bpv = __ffs((e0 | e1) | (e2 | e3)) - 1;

            float dn = mval + lt;
            if (mt > 0) { delta = dn; } else { bpv = j; }
            bp[(t - 1) * Cn + j] = (unsigned char)bpv;
        }

        // final scores / last tag
        float fin = delta + endt[j];
        float pm = fin;
#pragma unroll
        for (int o = 16; o; o >>= 1) pm = fmaxf(pm, __shfl_xor_sync(FULL, pm, o));
        unsigned bal = __ballot_sync(FULL, fin == pm);
        int last_tag = __ffs(bal) - 1;
        if (j == 0) path_out[b] = pm;

        __syncwarp();
        if (j == 0) {
            int tag = last_tag;
            tg[Tn - 1] = (unsigned char)tag;
            for (int t = Tn - 2; t >= 0; t--) {
                tag = bp[t * Cn + tag];
                tg[t] = (unsigned char)tag;
            }
        }
        __syncwarp();
#pragma unroll
        for (int idx = j; idx < Tn; idx += 32)
            tags_out[(size_t)b * Tn + idx] = (float)tg[idx];

    } else {
        // ---------------- gold score ----------------
        const int b = bid - 128;
        const int*   tgt = targets + b * Tn;
        const int*   mk  = mask + b * Tn;
        const float* lg  = logits + (size_t)b * Tn * Cn;

        float s = 0.f;
        int msum = 0;
        for (int t = j; t < Tn; t += 32) {
            int g  = tgt[t];
            int mi = mk[t];
            float mf = (float)mi;
            msum += mi;
            if (t >= 1)      s += trans[tgt[t - 1] * Cn + g] * mf;
            if (t <= Tn - 2) s += lg[t * Cn + g] * mf;
        }
#pragma unroll
        for (int o = 16; o; o >>= 1) {
            s    += __shfl_xor_sync(FULL, s, o);
            msum += __shfl_xor_sync(FULL, msum, o);
        }
        if (j == 0) {
            int li = msum - 1;
            int ltag = tgt[li];
            s += startt[tgt[0]];
            s += endt[ltag];
            s += lg[(Tn - 1) * Cn + ltag] * (float)mk[Tn - 1];
            g_score[b] = s;
            g_msum[b]  = msum;
        }
    }
}

// ---------------------------------------------------------------------------
// Kernel 3: loss = -sum_b(score_b - logZ_b) / sum(mask)
// ---------------------------------------------------------------------------
__global__ __launch_bounds__(64) void finalize_kernel(float* __restrict__ d_out)
{
    const unsigned FULL = 0xffffffffu;
    int tid = threadIdx.x;
    float d = g_score[tid] - g_logZ[tid];
    int   ms = g_msum[tid];
#pragma unroll
    for (int o = 16; o; o >>= 1) {
        d  += __shfl_xor_sync(FULL, d, o);
        ms += __shfl_xor_sync(FULL, ms, o);
    }
    __shared__ float sd[2];
    __shared__ int   sm[2];
    if ((tid & 31) == 0) { sd[tid >> 5] = d; sm[tid >> 5] = ms; }
    __syncthreads();
    if (tid == 0) {
        float total  = sd[0] + sd[1];
        int   mtotal = sm[0] + sm[1];
        d_out[0] = -total / (float)mtotal;
    }
}

// ---------------------------------------------------------------------------
// Launch
//   d_in: 0 vectors f32[B,T,D], 1 mask i32[B,T], 2 targets i32[B,T],
//         3 W f32[C,D], 4 b f32[C], 5 transitions f32[C,C],
//         6 start_transitions f32[C], 7 end_transitions f32[C]
//   d_out (f32): [loss(1), logits(B*T*C), tags(B*T), path_scores(B)]
// ---------------------------------------------------------------------------
extern "C" void kernel_launch(void* const* d_in, const int* in_sizes, int n_in,
                              void* d_out, int out_size)
{
    const float* V      = (const float*)d_in[0];
    const int*   mask   = (const int*)  d_in[1];
    const int*   tgt    = (const int*)  d_in[2];
    const float* W      = (const float*)d_in[3];
    const float* bias   = (const float*)d_in[4];
    const float* trans  = (const float*)d_in[5];
    const float* startt = (const float*)d_in[6];
    const float* endt   = (const float*)d_in[7];

    float* out    = (float*)d_out;
    float* logits = out + 1;
    float* tags   = out + 1 + (size_t)BT * Cn;
    float* path   = tags + BT;

    gemm_kernel<<<BT / 256, 256>>>(V, W, bias, logits);
    crf_kernel<<<192, 32>>>(logits, mask, tgt, trans, startt, endt, tags, path);
    finalize_kernel<<<1, 64>>>(out);
}

// round 12
// speedup vs baseline: 1.2606x; 1.2606x over previous
#include <cuda_runtime.h>
#include <cstdint>

// Problem constants
#define Bn 64
#define Tn 512
#define Dn 1024
#define Cn 32
#define BT (Bn*Tn)          // 32768

// Scratch (no device allocation allowed)
__device__ float g_Wt[Dn * Cn];   // W transposed: Wt[k][c]
__device__ float g_logZ[Bn];
__device__ float g_score[Bn];
__device__ int   g_msum[Bn];

// ---------------------------------------------------------------------------
// packed f32x2 helpers (Blackwell)
// ---------------------------------------------------------------------------
static __device__ __forceinline__ unsigned long long pack2(float lo, float hi) {
    unsigned long long r;
    asm("mov.b64 %0, {%1, %2};" : "=l"(r) : "f"(lo), "f"(hi));
    return r;
}
static __device__ __forceinline__ void unpack2(unsigned long long v, float& lo, float& hi) {
    asm("mov.b64 {%0, %1}, %2;" : "=f"(lo), "=f"(hi) : "l"(v));
}
static __device__ __forceinline__ void fma2(unsigned long long& d, unsigned long long a, unsigned long long b) {
    asm("fma.rn.f32x2 %0, %1, %2, %0;" : "+l"(d) : "l"(a), "l"(b));
}
static __device__ __forceinline__ unsigned long long mul2(unsigned long long a, unsigned long long b) {
    unsigned long long r;
    asm("mul.rn.f32x2 %0, %1, %2;" : "=l"(r) : "l"(a), "l"(b));
    return r;
}
static __device__ __forceinline__ unsigned long long add2(unsigned long long a, unsigned long long b) {
    unsigned long long r;
    asm("add.rn.f32x2 %0, %1, %2;" : "=l"(r) : "l"(a), "l"(b));
    return r;
}

// ---------------------------------------------------------------------------
// Kernel 0: transpose W [C,D] -> g_Wt [D,C] (coalesced writes)
// ---------------------------------------------------------------------------
__global__ __launch_bounds__(256) void prep_kernel(const float* __restrict__ W)
{
    int i = blockIdx.x * 256 + threadIdx.x;        // i = k*32 + c
    g_Wt[i] = W[(i & 31) * Dn + (i >> 5)];
}

// ---------------------------------------------------------------------------
// Kernel 1: logits = V @ W^T + b
//   256 blocks x 256 threads, 2 resident blocks/SM.
//   Thread = 2 rows x 8 cols, full K. W double-buffered in smem; V from
//   global with depth-2 register prefetch (each row read once from DRAM).
// ---------------------------------------------------------------------------
static __device__ __forceinline__ void kstep(float va, float vb,
                                             const float* swk,
                                             unsigned long long* acc)
{
    ulonglong2 w0 = *reinterpret_cast<const ulonglong2*>(swk);       // cols +0..3
    ulonglong2 w1 = *reinterpret_cast<const ulonglong2*>(swk + 4);   // cols +4..7
    unsigned long long a = pack2(va, va);
    unsigned long long b = pack2(vb, vb);
    fma2(acc[0], a, w0.x); fma2(acc[1], a, w0.y);
    fma2(acc[2], a, w1.x); fma2(acc[3], a, w1.y);
    fma2(acc[4], b, w0.x); fma2(acc[5], b, w0.y);
    fma2(acc[6], b, w1.x); fma2(acc[7], b, w1.y);
}

__global__ __launch_bounds__(256, 2) void gemm_kernel(
    const float* __restrict__ V,    // [BT, D]
    const float* __restrict__ bias, // [C]
    float* __restrict__ out)        // [BT, C] (4B aligned only)
{
    __shared__ __align__(16) float sW[2][128 * 32];   // 2 x 16 KB

    const int tid = threadIdx.x;
    const int rp  = tid >> 2;           // 0..63 -> row pair
    const int cq  = tid & 3;            // col group: cols cq*8..cq*8+7
    const size_t r0 = (size_t)blockIdx.x * 128 + rp * 2;

    const float4* vp0 = reinterpret_cast<const float4*>(V + r0 * Dn);
    const float4* vp1 = reinterpret_cast<const float4*>(V + (r0 + 1) * Dn);
    const float4* Wt4 = reinterpret_cast<const float4*>(g_Wt);

    unsigned long long acc[8];
#pragma unroll
    for (int p = 0; p < 4; p++) {
        unsigned long long bb = pack2(bias[cq * 8 + 2 * p], bias[cq * 8 + 2 * p + 1]);
        acc[p] = bb; acc[4 + p] = bb;
    }

    // prologue: stage chunk0, fetch chunk1 into regs
    float4 wreg[4];
#pragma unroll
    for (int i = 0; i < 4; i++) wreg[i] = Wt4[0 * 1024 + i * 256 + tid];
#pragma unroll
    for (int i = 0; i < 4; i++) reinterpret_cast<float4*>(sW[0])[i * 256 + tid] = wreg[i];
#pragma unroll
    for (int i = 0; i < 4; i++) wreg[i] = Wt4[1 * 1024 + i * 256 + tid];
    __syncthreads();

    // V register pipeline, depth 2
    float4 c0 = vp0[0], c1 = vp1[0];
    float4 p0 = vp0[1], p1 = vp1[1];

    for (int kc = 0; kc < 8; kc++) {
        const float* sb = sW[kc & 1];
        if (kc < 7) {
#pragma unroll
            for (int i = 0; i < 4; i++)
                reinterpret_cast<float4*>(sW[(kc & 1) ^ 1])[i * 256 + tid] = wreg[i];
        }
        if (kc < 6) {
#pragma unroll
            for (int i = 0; i < 4; i++)
                wreg[i] = Wt4[(kc + 2) * 1024 + i * 256 + tid];
        }
#pragma unroll 4
        for (int k4 = 0; k4 < 32; k4++) {
            int g = kc * 32 + k4;
            float4 n0 = c0, n1 = c1;
            if (g + 2 < 256) { n0 = vp0[g + 2]; n1 = vp1[g + 2]; }
            const float* swb = sb + k4 * 128 + cq * 8;
            kstep(c0.x, c1.x, swb +  0, acc);
            kstep(c0.y, c1.y, swb + 32, acc);
            kstep(c0.z, c1.z, swb + 64, acc);
            kstep(c0.w, c1.w, swb + 96, acc);
            c0 = p0; c1 = p1; p0 = n0; p1 = n1;
        }
        __syncthreads();
    }

    // scalar stores (base only 4B aligned)
    float* o0 = out + r0 * Cn + cq * 8;
    float* o1 = o0 + Cn;
#pragma unroll
    for (int p = 0; p < 4; p++) {
        float a, b;
        unpack2(acc[p], a, b);     o0[2 * p] = a; o0[2 * p + 1] = b;
        unpack2(acc[4 + p], a, b); o1[2 * p] = a; o1[2 * p + 1] = b;
    }
}

// ---------------------------------------------------------------------------
// Kernel 2: 192 one-warp blocks.
//   [0,64):   forward recursion in renormalized q-domain -> g_logZ[b]
//   [64,128): Viterbi recursion + backtrace -> tags, path_scores
//   [128,192): gold score -> g_score[b], g_msum[b]
// Cross-lane exchange via double-buffered smem row (STS + syncwarp + LDS.128).
// ---------------------------------------------------------------------------
__global__ __launch_bounds__(32) void crf_kernel(
    const float* __restrict__ logits,  // [B, T, C]
    const int*   __restrict__ mask,    // [B, T]
    const int*   __restrict__ targets, // [B, T]
    const float* __restrict__ trans,   // [C, C]
    const float* __restrict__ startt,  // [C]
    const float* __restrict__ endt,    // [C]
    float* __restrict__ tags_out,      // [B, T] as float
    float* __restrict__ path_out)      // [B]
{
    __shared__ __align__(16) float smq[2][Cn];
    __shared__ unsigned char bp[(Tn - 1) * Cn];
    __shared__ unsigned char tg[Tn];

    const unsigned FULL = 0xffffffffu;
    const int j = threadIdx.x;
    const int bid = blockIdx.x;

    if (bid < 64) {
        // ---------------- forward, q-domain with power-of-2 renorm ----------
        const int b = bid;
        unsigned long long E2[16];
#pragma unroll
        for (int q = 0; q < 16; q++)
            E2[q] = pack2(__expf(trans[(2 * q) * Cn + j]),
                          __expf(trans[(2 * q + 1) * Cn + j]));

        const float* lg = logits + (size_t)b * Tn * Cn + j;
        const int*   mk = mask + b * Tn;

        float qreg = __expf(startt[j] + lg[0]);
        smq[0][j] = qreg;
        int S = 0;

        float Lt1 = __expf(lg[Cn]);      int m1 = mk[1];
        float Lt2 = __expf(lg[2 * Cn]);  int m2 = mk[2];
        __syncwarp();

        for (int t = 1; t < Tn; t++) {
            float Lt = Lt1; int mt = m1;
            Lt1 = Lt2; m1 = m2;
            if (t + 2 < Tn) { Lt2 = __expf(lg[(t + 2) * Cn]); m2 = mk[t + 2]; }

            const ulonglong2* qp =
                reinterpret_cast<const ulonglong2*>(smq[(t - 1) & 1]);
            ulonglong2 v0 = qp[0], v1 = qp[1], v2 = qp[2], v3 = qp[3];
            ulonglong2 v4 = qp[4], v5 = qp[5], v6 = qp[6], v7 = qp[7];

            // uniform renorm factor from lane-0's q (exact power of two)
            float q0lo, q0hi; unpack2(v0.x, q0lo, q0hi);
            unsigned eb = __float_as_uint(q0lo) >> 23;
            float scale = __uint_as_float((254u - eb) << 23);
            int e = (int)eb - 127;

            unsigned long long s0 = mul2(v0.x, E2[0]);
            fma2(s0, v0.y, E2[1]);  fma2(s0, v1.x, E2[2]);  fma2(s0, v1.y, E2[3]);
            unsigned long long s1 = mul2(v2.x, E2[4]);
            fma2(s1, v2.y, E2[5]);  fma2(s1, v3.x, E2[6]);  fma2(s1, v3.y, E2[7]);
            unsigned long long s2 = mul2(v4.x, E2[8]);
            fma2(s2, v4.y, E2[9]);  fma2(s2, v5.x, E2[10]); fma2(s2, v5.y, E2[11]);
            unsigned long long s3 = mul2(v6.x, E2[12]);
            fma2(s3, v6.y, E2[13]); fma2(s3, v7.x, E2[14]); fma2(s3, v7.y, E2[15]);
            s0 = add2(s0, s1); s2 = add2(s2, s3); s0 = add2(s0, s2);
            float slo, shi; unpack2(s0, slo, shi);
            float s = slo + shi;

            float qn = s * Lt;
            float qs = (mt > 0) ? qn : qreg;
            qreg = qs * scale;
            S += e;
            smq[t & 1][j] = qreg;
            __syncwarp();
        }

        float v = qreg * __expf(endt[j]);
#pragma unroll
        for (int o = 16; o; o >>= 1) v += __shfl_xor_sync(FULL, v, o);
        if (j == 0)
            g_logZ[b] = (float)((double)S * 0.6931471805599453 + (double)logf(v));

    } else if (bid < 128) {
        // ---------------- Viterbi ----------------
        const int b = bid - 64;
        unsigned long long Tr2[16];
#pragma unroll
        for (int q = 0; q < 16; q++)
            Tr2[q] = pack2(trans[(2 * q) * Cn + j], trans[(2 * q + 1) * Cn + j]);

        const float* lg = logits + (size_t)b * Tn * Cn + j;
        const int*   mk = mask + b * Tn;

        float delta = startt[j] + lg[0];
        smq[0][j] = delta;

        float lt1 = lg[Cn];      int m1 = mk[1];
        float lt2 = lg[2 * Cn];  int m2 = mk[2];
        __syncwarp();

        for (int t = 1; t < Tn; t++) {
            float lt = lt1; int mt = m1;
            lt1 = lt2; m1 = m2;
            if (t + 2 < Tn) { lt2 = lg[(t + 2) * Cn]; m2 = mk[t + 2]; }

            const ulonglong2* qp =
                reinterpret_cast<const ulonglong2*>(smq[(t - 1) & 1]);
            ulonglong2 v0 = qp[0], v1 = qp[1], v2 = qp[2], v3 = qp[3];
            ulonglong2 v4 = qp[4], v5 = qp[5], v6 = qp[6], v7 = qp[7];

            float c[32];
            unsigned long long a;
            a = add2(v0.x, Tr2[0]);  unpack2(a, c[0],  c[1]);
            a = add2(v0.y, Tr2[1]);  unpack2(a, c[2],  c[3]);
            a = add2(v1.x, Tr2[2]);  unpack2(a, c[4],  c[5]);
            a = add2(v1.y, Tr2[3]);  unpack2(a, c[6],  c[7]);
            a = add2(v2.x, Tr2[4]);  unpack2(a, c[8],  c[9]);
            a = add2(v2.y, Tr2[5]);  unpack2(a, c[10], c[11]);
            a = add2(v3.x, Tr2[6]);  unpack2(a, c[12], c[13]);
            a = add2(v3.y, Tr2[7]);  unpack2(a, c[14], c[15]);
            a = add2(v4.x, Tr2[8]);  unpack2(a, c[16], c[17]);
            a = add2(v4.y, Tr2[9]);  unpack2(a, c[18], c[19]);
            a = add2(v5.x, Tr2[10]); unpack2(a, c[20], c[21]);
            a = add2(v5.y, Tr2[11]); unpack2(a, c[22], c[23]);
            a = add2(v6.x, Tr2[12]); unpack2(a, c[24], c[25]);
            a = add2(v6.y, Tr2[13]); unpack2(a, c[26], c[27]);
            a = add2(v7.x, Tr2[14]); unpack2(a, c[28], c[29]);
            a = add2(v7.y, Tr2[15]); unpack2(a, c[30], c[31]);

            float m16[16];
#pragma unroll
            for (int i = 0; i < 16; i++) m16[i] = fmaxf(c[2 * i], c[2 * i + 1]);
#pragma unroll
            for (int i = 0; i < 8; i++)  m16[i] = fmaxf(m16[2 * i], m16[2 * i + 1]);
#pragma unroll
            for (int i = 0; i < 4; i++)  m16[i] = fmaxf(m16[2 * i], m16[2 * i + 1]);
            m16[0] = fmaxf(m16[0], m16[1]);
            m16[1] = fmaxf(m16[2], m16[3]);
            float mval = fmaxf(m16[0], m16[1]);

            unsigned e0 = 0, e1 = 0, e2 = 0, e3 = 0;
#pragma unroll
            for (int i = 0; i < 32; i += 4) {
                e0 |= (c[i]     == mval) ? (1u << i)       : 0u;
                e1 |= (c[i + 1] == mval) ? (1u << (i + 1)) : 0u;
                e2 |= (c[i + 2] == mval) ? (1u << (i + 2)) : 0u;
                e3 |= (c[i + 3] == mval) ? (1u << (i + 3)) : 0u;
            }
            int bpv = __ffs((e0 | e1) | (e2 | e3)) - 1;

            float dn = mval + lt;
            if (mt > 0) { delta = dn; } else { bpv = j; }
            smq[t & 1][j] = delta;
            bp[(t - 1) * Cn + j] = (unsigned char)bpv;
            __syncwarp();
        }

        float fin = delta + endt[j];
        float pm = fin;
#pragma unroll
        for (int o = 16; o; o >>= 1) pm = fmaxf(pm, __shfl_xor_sync(FULL, pm, o));
        unsigned bal = __ballot_sync(FULL, fin == pm);
        int last_tag = __ffs(bal) - 1;
        if (j == 0) path_out[b] = pm;

        __syncwarp();
        if (j == 0) {
            int tag = last_tag;
            tg[Tn - 1] = (unsigned char)tag;
            for (int t = Tn - 2; t >= 0; t--) {
                tag = bp[t * Cn + tag];
                tg[t] = (unsigned char)tag;
            }
        }
        __syncwarp();
#pragma unroll
        for (int idx = j; idx < Tn; idx += 32)
            tags_out[(size_t)b * Tn + idx] = (float)tg[idx];

    } else {
        // ---------------- gold score ----------------
        const int b = bid - 128;
        const int*   tgt = targets + b * Tn;
        const int*   mk  = mask + b * Tn;
        const float* lg  = logits + (size_t)b * Tn * Cn;

        float s = 0.f;
        int msum = 0;
        for (int t = j; t < Tn; t += 32) {
            int g  = tgt[t];
            int mi = mk[t];
            float mf = (float)mi;
            msum += mi;
            if (t >= 1)      s += trans[tgt[t - 1] * Cn + g] * mf;
            if (t <= Tn - 2) s += lg[t * Cn + g] * mf;
        }
#pragma unroll
        for (int o = 16; o; o >>= 1) {
            s    += __shfl_xor_sync(FULL, s, o);
            msum += __shfl_xor_sync(FULL, msum, o);
        }
        if (j == 0) {
            int li = msum - 1;
            int ltag = tgt[li];
            s += startt[tgt[0]];
            s += endt[ltag];
            s += lg[(Tn - 1) * Cn + ltag] * (float)mk[Tn - 1];
            g_score[b] = s;
            g_msum[b]  = msum;
        }
    }
}

// ---------------------------------------------------------------------------
// Kernel 3: loss = -sum_b(score_b - logZ_b) / sum(mask)
// ---------------------------------------------------------------------------
__global__ __launch_bounds__(64) void finalize_kernel(float* __restrict__ d_out)
{
    const unsigned FULL = 0xffffffffu;
    int tid = threadIdx.x;
    float d = g_score[tid] - g_logZ[tid];
    int   ms = g_msum[tid];
#pragma unroll
    for (int o = 16; o; o >>= 1) {
        d  += __shfl_xor_sync(FULL, d, o);
        ms += __shfl_xor_sync(FULL, ms, o);
    }
    __shared__ float sd[2];
    __shared__ int   sm[2];
    if ((tid & 31) == 0) { sd[tid >> 5] = d; sm[tid >> 5] = ms; }
    __syncthreads();
    if (tid == 0) {
        float total  = sd[0] + sd[1];
        int   mtotal = sm[0] + sm[1];
        d_out[0] = -total / (float)mtotal;
    }
}

// ---------------------------------------------------------------------------
// Launch
//   d_in: 0 vectors f32[B,T,D], 1 mask i32[B,T], 2 targets i32[B,T],
//         3 W f32[C,D], 4 b f32[C], 5 transitions f32[C,C],
//         6 start_transitions f32[C], 7 end_transitions f32[C]
//   d_out (f32): [loss(1), logits(B*T*C), tags(B*T), path_scores(B)]
// ---------------------------------------------------------------------------
extern "C" void kernel_launch(void* const* d_in, const int* in_sizes, int n_in,
                              void* d_out, int out_size)
{
    const float* V      = (const float*)d_in[0];
    const int*   mask   = (const int*)  d_in[1];
    const int*   tgt    = (const int*)  d_in[2];
    const float* W      = (const float*)d_in[3];
    const float* bias   = (const float*)d_in[4];
    const float* trans  = (const float*)d_in[5];
    const float* startt = (const float*)d_in[6];
    const float* endt   = (const float*)d_in[7];

    float* out    = (float*)d_out;
    float* logits = out + 1;
    float* tags   = out + 1 + (size_t)BT * Cn;
    float* path   = tags + BT;

    prep_kernel<<<128, 256>>>(W);
    gemm_kernel<<<256, 256>>>(V, bias, logits);
    crf_kernel<<<192, 32>>>(logits, mask, tgt, trans, startt, endt, tags, path);
    finalize_kernel<<<1, 64>>>(out);
}

// round 13
// speedup vs baseline: 1.4191x; 1.1257x over previous
#include <cuda_runtime.h>
#include <cstdint>

// Problem constants
#define Bn 64
#define Tn 512
#define Dn 1024
#define Cn 32
#define BT (Bn*Tn)          // 32768

// Scratch (no device allocation allowed)
__device__ float g_Wt[Dn * Cn];   // W transposed: Wt[k][c]
__device__ float g_logZ[Bn];
__device__ float g_score[Bn];
__device__ int   g_msum[Bn];

// ---------------------------------------------------------------------------
// packed f32x2 helpers (Blackwell)
// ---------------------------------------------------------------------------
static __device__ __forceinline__ unsigned long long pack2(float lo, float hi) {
    unsigned long long r;
    asm("mov.b64 %0, {%1, %2};" : "=l"(r) : "f"(lo), "f"(hi));
    return r;
}
static __device__ __forceinline__ void unpack2(unsigned long long v, float& lo, float& hi) {
    asm("mov.b64 {%0, %1}, %2;" : "=f"(lo), "=f"(hi) : "l"(v));
}
static __device__ __forceinline__ void fma2(unsigned long long& d, unsigned long long a, unsigned long long b) {
    asm("fma.rn.f32x2 %0, %1, %2, %0;" : "+l"(d) : "l"(a), "l"(b));
}
static __device__ __forceinline__ unsigned long long mul2(unsigned long long a, unsigned long long b) {
    unsigned long long r;
    asm("mul.rn.f32x2 %0, %1, %2;" : "=l"(r) : "l"(a), "l"(b));
    return r;
}
static __device__ __forceinline__ unsigned long long add2(unsigned long long a, unsigned long long b) {
    unsigned long long r;
    asm("add.rn.f32x2 %0, %1, %2;" : "=l"(r) : "l"(a), "l"(b));
    return r;
}

// ---------------------------------------------------------------------------
// Kernel 0: transpose W [C,D] -> g_Wt [D,C]
// ---------------------------------------------------------------------------
__global__ __launch_bounds__(256) void prep_kernel(const float* __restrict__ W)
{
    int i = blockIdx.x * 256 + threadIdx.x;        // i = k*32 + c
    g_Wt[i] = W[(i & 31) * Dn + (i >> 5)];
}

// ---------------------------------------------------------------------------
// Kernel 1: logits = V @ W^T + b
//   256 blocks x 256 threads, 2 resident blocks/SM.
//   Thread = 2 rows x 8 cols, full K. W double-buffered in smem; V from
//   global with depth-2 register prefetch (each row read once from DRAM).
// ---------------------------------------------------------------------------
static __device__ __forceinline__ void kstep(float va, float vb,
                                             const float* swk,
                                             unsigned long long* acc)
{
    ulonglong2 w0 = *reinterpret_cast<const ulonglong2*>(swk);       // cols +0..3
    ulonglong2 w1 = *reinterpret_cast<const ulonglong2*>(swk + 4);   // cols +4..7
    unsigned long long a = pack2(va, va);
    unsigned long long b = pack2(vb, vb);
    fma2(acc[0], a, w0.x); fma2(acc[1], a, w0.y);
    fma2(acc[2], a, w1.x); fma2(acc[3], a, w1.y);
    fma2(acc[4], b, w0.x); fma2(acc[5], b, w0.y);
    fma2(acc[6], b, w1.x); fma2(acc[7], b, w1.y);
}

__global__ __launch_bounds__(256, 2) void gemm_kernel(
    const float* __restrict__ V,    // [BT, D]
    const float* __restrict__ bias, // [C]
    float* __restrict__ out)        // [BT, C] (4B aligned only)
{
    __shared__ __align__(16) float sW[2][128 * 32];   // 2 x 16 KB

    const int tid = threadIdx.x;
    const int rp  = tid >> 2;           // 0..63 -> row pair
    const int cq  = tid & 3;            // col group: cols cq*8..cq*8+7
    const size_t r0 = (size_t)blockIdx.x * 128 + rp * 2;

    const float4* vp0 = reinterpret_cast<const float4*>(V + r0 * Dn);
    const float4* vp1 = reinterpret_cast<const float4*>(V + (r0 + 1) * Dn);
    const float4* Wt4 = reinterpret_cast<const float4*>(g_Wt);

    unsigned long long acc[8];
#pragma unroll
    for (int p = 0; p < 4; p++) {
        unsigned long long bb = pack2(bias[cq * 8 + 2 * p], bias[cq * 8 + 2 * p + 1]);
        acc[p] = bb; acc[4 + p] = bb;
    }

    // prologue: stage chunk0, fetch chunk1 into regs
    float4 wreg[4];
#pragma unroll
    for (int i = 0; i < 4; i++) wreg[i] = Wt4[0 * 1024 + i * 256 + tid];
#pragma unroll
    for (int i = 0; i < 4; i++) reinterpret_cast<float4*>(sW[0])[i * 256 + tid] = wreg[i];
#pragma unroll
    for (int i = 0; i < 4; i++) wreg[i] = Wt4[1 * 1024 + i * 256 + tid];
    __syncthreads();

    // V register pipeline, depth 2
    float4 c0 = vp0[0], c1 = vp1[0];
    float4 p0 = vp0[1], p1 = vp1[1];

    for (int kc = 0; kc < 8; kc++) {
        const float* sb = sW[kc & 1];
        if (kc < 7) {
#pragma unroll
            for (int i = 0; i < 4; i++)
                reinterpret_cast<float4*>(sW[(kc & 1) ^ 1])[i * 256 + tid] = wreg[i];
        }
        if (kc < 6) {
#pragma unroll
            for (int i = 0; i < 4; i++)
                wreg[i] = Wt4[(kc + 2) * 1024 + i * 256 + tid];
        }
#pragma unroll 4
        for (int k4 = 0; k4 < 32; k4++) {
            int g = kc * 32 + k4;
            float4 n0 = c0, n1 = c1;
            if (g + 2 < 256) { n0 = vp0[g + 2]; n1 = vp1[g + 2]; }
            const float* swb = sb + k4 * 128 + cq * 8;
            kstep(c0.x, c1.x, swb +  0, acc);
            kstep(c0.y, c1.y, swb + 32, acc);
            kstep(c0.z, c1.z, swb + 64, acc);
            kstep(c0.w, c1.w, swb + 96, acc);
            c0 = p0; c1 = p1; p0 = n0; p1 = n1;
        }
        __syncthreads();
    }

    // scalar stores (base only 4B aligned)
    float* o0 = out + r0 * Cn + cq * 8;
    float* o1 = o0 + Cn;
#pragma unroll
    for (int p = 0; p < 4; p++) {
        float a, b;
        unpack2(acc[p], a, b);     o0[2 * p] = a; o0[2 * p + 1] = b;
        unpack2(acc[4 + p], a, b); o1[2 * p] = a; o1[2 * p + 1] = b;
    }
}

// ---------------------------------------------------------------------------
// Kernel 2: 192 one-warp blocks, dynamic smem.
//   [0,64):   forward recursion (q-domain, pow2 renorm) -> g_logZ[b]
//   [64,128): Viterbi recursion + backtrace -> tags, path_scores
//   [128,192): gold score -> g_score[b], g_msum[b]
// Each fwd/vit block first copies its [T,C] logits slice + mask into smem
// (bulk, coalesced, MLP-deep), so the sequential recursion never touches
// DRAM/L2 latency on its dependency chain.
//
// Dynamic smem layout (bytes):
//   [0, 65536)        float sL[Tn*Cn]      logits slice
//   [65536, 67584)    int   sM[Tn]         mask
//   [67584, 67840)    float smq[2][32]     exchange rows (16B aligned)
//   [67840, 84192)    uchar bp[(Tn-1)*Cn]  backpointers (vit)
//   [84192, 84704)    uchar tg[Tn]         backtraced tags (vit)
// ---------------------------------------------------------------------------
#define CRF_SMEM 84736

__global__ __launch_bounds__(32) void crf_kernel(
    const float* __restrict__ logits,  // [B, T, C]  (4B aligned only)
    const int*   __restrict__ mask,    // [B, T]
    const int*   __restrict__ targets, // [B, T]
    const float* __restrict__ trans,   // [C, C]
    const float* __restrict__ startt,  // [C]
    const float* __restrict__ endt,    // [C]
    float* __restrict__ tags_out,      // [B, T] as float
    float* __restrict__ path_out)      // [B]
{
    extern __shared__ __align__(16) unsigned char dsm[];
    float*         sL  = reinterpret_cast<float*>(dsm);
    int*           sM  = reinterpret_cast<int*>(dsm + 65536);
    float*         smq = reinterpret_cast<float*>(dsm + 67584);
    unsigned char* bp  = dsm + 67840;
    unsigned char* tg  = dsm + 84192;

    const unsigned FULL = 0xffffffffu;
    const int j = threadIdx.x;
    const int bid = blockIdx.x;

    if (bid < 128) {
        // -------- bulk-load this batch's logits slice + mask into smem -----
        const int b = bid & 63;
        const float* lgg = logits + (size_t)b * Tn * Cn;
        const int*   mkg = mask + b * Tn;
#pragma unroll 8
        for (int i = j; i < Tn * Cn; i += 32) sL[i] = lgg[i];
#pragma unroll 4
        for (int t = j; t < Tn; t += 32) sM[t] = mkg[t];
        __syncwarp();

        if (bid < 64) {
            // ---------------- forward, q-domain, pow2 renorm ----------------
            unsigned long long E2[16];
#pragma unroll
            for (int q = 0; q < 16; q++)
                E2[q] = pack2(__expf(trans[(2 * q) * Cn + j]),
                              __expf(trans[(2 * q + 1) * Cn + j]));

            float qreg = __expf(startt[j] + sL[j]);
            smq[j] = qreg;
            int S = 0;

            float Lt_n = __expf(sL[Cn + j]);
            int   m_n  = sM[1];
            __syncwarp();

            for (int t = 1; t < Tn; t++) {
                float Lt = Lt_n; int mt = m_n;
                if (t + 1 < Tn) { Lt_n = __expf(sL[(t + 1) * Cn + j]); m_n = sM[t + 1]; }

                const ulonglong2* qp =
                    reinterpret_cast<const ulonglong2*>(smq + ((t - 1) & 1) * Cn);
                ulonglong2 v0 = qp[0], v1 = qp[1], v2 = qp[2], v3 = qp[3];
                ulonglong2 v4 = qp[4], v5 = qp[5], v6 = qp[6], v7 = qp[7];

                // uniform renorm factor from lane-0's q (exact power of two)
                float q0lo, q0hi; unpack2(v0.x, q0lo, q0hi);
                unsigned eb = __float_as_uint(q0lo) >> 23;
                float scale = __uint_as_float((254u - eb) << 23);
                int e = (int)eb - 127;

                unsigned long long s0 = mul2(v0.x, E2[0]);
                fma2(s0, v0.y, E2[1]);  fma2(s0, v1.x, E2[2]);  fma2(s0, v1.y, E2[3]);
                unsigned long long s1 = mul2(v2.x, E2[4]);
                fma2(s1, v2.y, E2[5]);  fma2(s1, v3.x, E2[6]);  fma2(s1, v3.y, E2[7]);
                unsigned long long s2 = mul2(v4.x, E2[8]);
                fma2(s2, v4.y, E2[9]);  fma2(s2, v5.x, E2[10]); fma2(s2, v5.y, E2[11]);
                unsigned long long s3 = mul2(v6.x, E2[12]);
                fma2(s3, v6.y, E2[13]); fma2(s3, v7.x, E2[14]); fma2(s3, v7.y, E2[15]);
                s0 = add2(s0, s1); s2 = add2(s2, s3); s0 = add2(s0, s2);
                float slo, shi; unpack2(s0, slo, shi);
                float s = slo + shi;

                float qn = s * Lt;
                float qs = (mt > 0) ? qn : qreg;
                qreg = qs * scale;
                S += e;
                smq[(t & 1) * Cn + j] = qreg;
                __syncwarp();
            }

            float v = qreg * __expf(endt[j]);
#pragma unroll
            for (int o = 16; o; o >>= 1) v += __shfl_xor_sync(FULL, v, o);
            if (j == 0)
                g_logZ[b] = (float)((double)S * 0.6931471805599453 + (double)logf(v));

        } else {
            // ---------------- Viterbi ----------------
            unsigned long long Tr2[16];
#pragma unroll
            for (int q = 0; q < 16; q++)
                Tr2[q] = pack2(trans[(2 * q) * Cn + j], trans[(2 * q + 1) * Cn + j]);

            float delta = startt[j] + sL[j];
            smq[j] = delta;

            float lt_n = sL[Cn + j];
            int   m_n  = sM[1];
            __syncwarp();

            for (int t = 1; t < Tn; t++) {
                float lt = lt_n; int mt = m_n;
                if (t + 1 < Tn) { lt_n = sL[(t + 1) * Cn + j]; m_n = sM[t + 1]; }

                const ulonglong2* qp =
                    reinterpret_cast<const ulonglong2*>(smq + ((t - 1) & 1) * Cn);
                ulonglong2 v0 = qp[0], v1 = qp[1], v2 = qp[2], v3 = qp[3];
                ulonglong2 v4 = qp[4], v5 = qp[5], v6 = qp[6], v7 = qp[7];

                float c[32];
                unsigned long long a;
                a = add2(v0.x, Tr2[0]);  unpack2(a, c[0],  c[1]);
                a = add2(v0.y, Tr2[1]);  unpack2(a, c[2],  c[3]);
                a = add2(v1.x, Tr2[2]);  unpack2(a, c[4],  c[5]);
                a = add2(v1.y, Tr2[3]);  unpack2(a, c[6],  c[7]);
                a = add2(v2.x, Tr2[4]);  unpack2(a, c[8],  c[9]);
                a = add2(v2.y, Tr2[5]);  unpack2(a, c[10], c[11]);
                a = add2(v3.x, Tr2[6]);  unpack2(a, c[12], c[13]);
                a = add2(v3.y, Tr2[7]);  unpack2(a, c[14], c[15]);
                a = add2(v4.x, Tr2[8]);  unpack2(a, c[16], c[17]);
                a = add2(v4.y, Tr2[9]);  unpack2(a, c[18], c[19]);
                a = add2(v5.x, Tr2[10]); unpack2(a, c[20], c[21]);
                a = add2(v5.y, Tr2[11]); unpack2(a, c[22], c[23]);
                a = add2(v6.x, Tr2[12]); unpack2(a, c[24], c[25]);
                a = add2(v6.y, Tr2[13]); unpack2(a, c[26], c[27]);
                a = add2(v7.x, Tr2[14]); unpack2(a, c[28], c[29]);
                a = add2(v7.y, Tr2[15]); unpack2(a, c[30], c[31]);

                float m16[16];
#pragma unroll
                for (int i = 0; i < 16; i++) m16[i] = fmaxf(c[2 * i], c[2 * i + 1]);
#pragma unroll
                for (int i = 0; i < 8; i++)  m16[i] = fmaxf(m16[2 * i], m16[2 * i + 1]);
#pragma unroll
                for (int i = 0; i < 4; i++)  m16[i] = fmaxf(m16[2 * i], m16[2 * i + 1]);
                m16[0] = fmaxf(m16[0], m16[1]);
                m16[1] = fmaxf(m16[2], m16[3]);
                float mval = fmaxf(m16[0], m16[1]);

                unsigned e0 = 0, e1 = 0, e2 = 0, e3 = 0;
#pragma unroll
                for (int i = 0; i < 32; i += 4) {
                    e0 |= (c[i]     == mval) ? (1u << i)       : 0u;
                    e1 |= (c[i + 1] == mval) ? (1u << (i + 1)) : 0u;
                    e2 |= (c[i + 2] == mval) ? (1u << (i + 2)) : 0u;
                    e3 |= (c[i + 3] == mval) ? (1u << (i + 3)) : 0u;
                }
                int bpv = __ffs((e0 | e1) | (e2 | e3)) - 1;

                float dn = mval + lt;
                if (mt > 0) { delta = dn; } else { bpv = j; }
                smq[(t & 1) * Cn + j] = delta;
                bp[(t - 1) * Cn + j] = (unsigned char)bpv;
                __syncwarp();
            }

            float fin = delta + endt[j];
            float pm = fin;
#pragma unroll
            for (int o = 16; o; o >>= 1) pm = fmaxf(pm, __shfl_xor_sync(FULL, pm, o));
            unsigned bal = __ballot_sync(FULL, fin == pm);
            int last_tag = __ffs(bal) - 1;
            if (j == 0) path_out[b] = pm;

            __syncwarp();
            if (j == 0) {
                int tag = last_tag;
                tg[Tn - 1] = (unsigned char)tag;
                for (int t = Tn - 2; t >= 0; t--) {
                    tag = bp[t * Cn + tag];
                    tg[t] = (unsigned char)tag;
                }
            }
            __syncwarp();
#pragma unroll
            for (int idx = j; idx < Tn; idx += 32)
                tags_out[(size_t)b * Tn + idx] = (float)tg[idx];
        }

    } else {
        // ---------------- gold score ----------------
        const int b = bid - 128;
        const int*   tgt = targets + b * Tn;
        const int*   mk  = mask + b * Tn;
        const float* lg  = logits + (size_t)b * Tn * Cn;

        float s = 0.f;
        int msum = 0;
        for (int t = j; t < Tn; t += 32) {
            int g  = tgt[t];
            int mi = mk[t];
            float mf = (float)mi;
            msum += mi;
            if (t >= 1)      s += trans[tgt[t - 1] * Cn + g] * mf;
            if (t <= Tn - 2) s += lg[t * Cn + g] * mf;
        }
#pragma unroll
        for (int o = 16; o; o >>= 1) {
            s    += __shfl_xor_sync(FULL, s, o);
            msum += __shfl_xor_sync(FULL, msum, o);
        }
        if (j == 0) {
            int li = msum - 1;
            int ltag = tgt[li];
            s += startt[tgt[0]];
            s += endt[ltag];
            s += lg[(Tn - 1) * Cn + ltag] * (float)mk[Tn - 1];
            g_score[b] = s;
            g_msum[b]  = msum;
        }
    }
}

// ---------------------------------------------------------------------------
// Kernel 3: loss = -sum_b(score_b - logZ_b) / sum(mask)
// ---------------------------------------------------------------------------
__global__ __launch_bounds__(64) void finalize_kernel(float* __restrict__ d_out)
{
    const unsigned FULL = 0xffffffffu;
    int tid = threadIdx.x;
    float d = g_score[tid] - g_logZ[tid];
    int   ms = g_msum[tid];
#pragma unroll
    for (int o = 16; o; o >>= 1) {
        d  += __shfl_xor_sync(FULL, d, o);
        ms += __shfl_xor_sync(FULL, ms, o);
    }
    __shared__ float sd[2];
    __shared__ int   sm[2];
    if ((tid & 31) == 0) { sd[tid >> 5] = d; sm[tid >> 5] = ms; }
    __syncthreads();
    if (tid == 0) {
        float total  = sd[0] + sd[1];
        int   mtotal = sm[0] + sm[1];
        d_out[0] = -total / (float)mtotal;
    }
}

// ---------------------------------------------------------------------------
// Launch
//   d_in: 0 vectors f32[B,T,D], 1 mask i32[B,T], 2 targets i32[B,T],
//         3 W f32[C,D], 4 b f32[C], 5 transitions f32[C,C],
//         6 start_transitions f32[C], 7 end_transitions f32[C]
//   d_out (f32): [loss(1), logits(B*T*C), tags(B*T), path_scores(B)]
// ---------------------------------------------------------------------------
extern "C" void kernel_launch(void* const* d_in, const int* in_sizes, int n_in,
                              void* d_out, int out_size)
{
    const float* V      = (const float*)d_in[0];
    const int*   mask   = (const int*)  d_in[1];
    const int*   tgt    = (const int*)  d_in[2];
    const float* W      = (const float*)d_in[3];
    const float* bias   = (const float*)d_in[4];
    const float* trans  = (const float*)d_in[5];
    const float* startt = (const float*)d_in[6];
    const float* endt   = (const float*)d_in[7];

    float* out    = (float*)d_out;
    float* logits = out + 1;
    float* tags   = out + 1 + (size_t)BT * Cn;
    float* path   = tags + BT;

    static int s_attr_done = 0;
    if (!s_attr_done) {
        cudaFuncSetAttribute(crf_kernel,
                             cudaFuncAttributeMaxDynamicSharedMemorySize,
                             CRF_SMEM);
        s_attr_done = 1;
    }

    prep_kernel<<<128, 256>>>(W);
    gemm_kernel<<<256, 256>>>(V, bias, logits);
    crf_kernel<<<192, 32, CRF_SMEM>>>(logits, mask, tgt, trans, startt, endt,
                                      tags, path);
    finalize_kernel<<<1, 64>>>(out);
}